// round 14
// baseline (speedup 1.0000x reference)
#include <cuda_runtime.h>
#include <cuda_fp16.h>
#include <math.h>
#include <cstdint>

// ===========================================================================
// STCNNT cell, convs as implicit GEMM on mma.sync (HMMA fp16 single product,
// fp32 accum). Activations fp16 CHANNEL-LAST [n][row][col][ci].
// Round-13 conv core unchanged; QK restructured (smem-staged, 16x less L2
// traffic); v stored fp16.
// B=4, T=32 (BT=128), C=32, H=W=64, mixer=128, n_head=8
// ===========================================================================

#define BT 128

// ---------------- device scratch (zero-initialized at module load) ---------
__device__ __half g_xpad[BT * 66 * 66 * 32];     // fp16 padded channel-last
__device__ __half g_ypad[BT * 66 * 66 * 32];
__device__ __half g_hpad[BT * 66 * 66 * 128];
__device__ __half g_v  [BT * 64 * 64 * 32];      // fp16 channel-last
__device__ float  g_kq [BT * 64 * 32 * 32];      // [n][64: k=0-31,q=32-63][32][32]
__device__ float  g_scr[4 * 32 * 32 * 32];       // QK partials [dq][bh][t][s]
__device__ float  g_att[4 * 8 * 32 * 32];
__device__ float  g_x1 [BT * 32 * 64 * 64];      // standard layout
#define WSTRIDE 46080   // halfs per conv slot: max KB*9*COUT*40
__device__ __align__(16) __half g_wb[5 * WSTRIDE];

__device__ __forceinline__ float gelu_f(float v) {
    float u = 0.7978845608028654f * (v + 0.044715f * v * v * v);
    return 0.5f * v * (1.0f + tanhf(u));
}

__device__ __forceinline__ uint32_t smem_to_u32(const void* p) {
    uint32_t a;
    asm("{ .reg .u64 t; cvta.to.shared.u64 t, %1; cvt.u32.u64 %0, t; }" : "=r"(a) : "l"(p));
    return a;
}

__device__ __forceinline__ void mma_f16(float* c, uint32_t a0, uint32_t a1,
                                        uint32_t a2, uint32_t a3,
                                        uint32_t b0, uint32_t b1) {
    asm volatile(
        "mma.sync.aligned.m16n8k16.row.col.f32.f16.f16.f32 "
        "{%0,%1,%2,%3}, {%4,%5,%6,%7}, {%8,%9}, {%0,%1,%2,%3};"
        : "+f"(c[0]), "+f"(c[1]), "+f"(c[2]), "+f"(c[3])
        : "r"(a0), "r"(a1), "r"(a2), "r"(a3), "r"(b0), "r"(b1));
}

// ---------------------------------------------------------------------------
// merged weight prep: fp32 [cout][Cin][3][3] -> fp16 planes for all 5 slots,
// layout [cib][tap][COUTL][40] (k 0..31 real, 32..39 zero)
// ---------------------------------------------------------------------------
__device__ __forceinline__ void wprep_one(const float* w, __half* dstp, int idx,
                                          int CIN, int COUTL, int cout0, int NCO) {
    int kk = idx % 40;
    int t1 = idx / 40;
    int cout = t1 % NCO;
    int t2 = t1 / NCO;
    int tap = t2 % 9, cib = t2 / 9;
    float wv = (kk < 32) ? w[((size_t)cout * CIN + cib * 32 + kk) * 9 + tap] : 0.f;
    dstp[((size_t)(cib * 9 + tap) * COUTL + cout0 + cout) * 40 + kk] = __float2half_rn(wv);
}

__global__ void wprep_all(const float* __restrict__ Wv, const float* __restrict__ Wk,
                          const float* __restrict__ Wq, const float* __restrict__ Wo,
                          const float* __restrict__ Wm1, const float* __restrict__ Wm2,
                          __half* __restrict__ wb) {
    int idx = blockIdx.x * blockDim.x + threadIdx.x;
    if (idx < 11520) {
        wprep_one(Wv, wb + 0 * WSTRIDE, idx, 32, 32, 0, 32);
    } else if (idx < 23040) {
        wprep_one(Wk, wb + 1 * WSTRIDE, idx - 11520, 32, 64, 0, 32);
    } else if (idx < 34560) {
        wprep_one(Wq, wb + 1 * WSTRIDE, idx - 23040, 32, 64, 32, 32);
    } else if (idx < 46080) {
        wprep_one(Wo, wb + 2 * WSTRIDE, idx - 34560, 32, 32, 0, 32);
    } else if (idx < 92160) {
        wprep_one(Wm1, wb + 3 * WSTRIDE, idx - 46080, 32, 128, 0, 128);
    } else if (idx < 138240) {
        wprep_one(Wm2, wb + 4 * WSTRIDE, idx - 92160, 128, 32, 0, 32);
    }
}

// ---------------------------------------------------------------------------
// LayerNorm over (C,H,W)=131072 -> fp16 padded CHANNEL-LAST [n][66][66][32]
// grid=128, block=256
// ---------------------------------------------------------------------------
__global__ void ln_pad_kernel(const float* __restrict__ x, const float* __restrict__ g,
                              const float* __restrict__ b, __half* __restrict__ out) {
    int n = blockIdx.x;
    const float* xb = x + (size_t)n * 131072;
    const float4* x4 = (const float4*)xb;
    float s = 0.f, ss = 0.f;
    for (int i = threadIdx.x; i < 32768; i += 256) {
        float4 v = x4[i];
        s  += v.x + v.y + v.z + v.w;
        ss += v.x * v.x + v.y * v.y + v.z * v.z + v.w * v.w;
    }
    __shared__ float rs[8], rss[8];
    #pragma unroll
    for (int o = 16; o > 0; o >>= 1) {
        s  += __shfl_xor_sync(0xffffffffu, s, o);
        ss += __shfl_xor_sync(0xffffffffu, ss, o);
    }
    int wrp = threadIdx.x >> 5, lane = threadIdx.x & 31;
    if (lane == 0) { rs[wrp] = s; rss[wrp] = ss; }
    __syncthreads();
    if (threadIdx.x < 32) {
        s  = (threadIdx.x < 8) ? rs[threadIdx.x]  : 0.f;
        ss = (threadIdx.x < 8) ? rss[threadIdx.x] : 0.f;
        #pragma unroll
        for (int o = 4; o > 0; o >>= 1) {
            s  += __shfl_xor_sync(0xffffffffu, s, o);
            ss += __shfl_xor_sync(0xffffffffu, ss, o);
        }
        if (threadIdx.x == 0) { rs[0] = s; rss[0] = ss; }
    }
    __syncthreads();
    float mean = rs[0] * (1.f / 131072.f);
    float var  = rss[0] * (1.f / 131072.f) - mean * mean;
    float rstd = rsqrtf(var + 1e-5f);

    __shared__ float tile[32][33];
    __half* ob = out + (size_t)n * 4356 * 32;
    for (int t0 = 0; t0 < 4096; t0 += 32) {
        __syncthreads();
        #pragma unroll
        for (int cc = 0; cc < 4; cc++) {
            int ci = wrp * 4 + cc;
            int px = t0 + lane;
            size_t e = (size_t)ci * 4096 + px;
            tile[ci][lane] = (xb[e] - mean) * rstd * __ldg(g + e) + __ldg(b + e);
        }
        __syncthreads();
        #pragma unroll
        for (int cc = 0; cc < 4; cc++) {
            int pxl = wrp * 4 + cc;
            int px = t0 + pxl;
            int y = px >> 6, xx = px & 63;
            ob[((y + 1) * 66 + (xx + 1)) * 32 + lane] = __float2half(tile[lane][pxl]);
        }
    }
}

// ---------------------------------------------------------------------------
// HMMA implicit-GEMM 3x3 conv (round-13 core, unchanged).
// OM: 0 = fp32 standard out (+res), 1 = fp16 padded channel-last,
//     2 = fp16 channel-last (v)
// ---------------------------------------------------------------------------
template<int CIN, int COUT, int STRIDE, int NT, int CB, bool HASBIAS, bool DOGELU, bool RES, int OM>
__global__ void __launch_bounds__(256) convT(
    const __half* __restrict__ in,
    const __half* __restrict__ wph,
    const float* __restrict__ bias,
    const float* __restrict__ res,
    void* __restrict__ outv, int by0) {

    constexpr int WOUT  = 64 / STRIDE;
    constexpr int PIX   = NT * 64;
    constexpr int RPT   = PIX / WOUT;
    constexpr int NR    = (RPT - 1) * STRIDE + 3;
    constexpr int KB    = CIN / 32;
    constexpr int S_INH = NR * 66 * 40;   // halfs
    constexpr int S_WH  = 9 * 32 * 40;    // halfs

    extern __shared__ __align__(16) __half smem[];
    __half* s_in = smem;
    __half* s_wh = smem + S_INH;
    uint32_t sin_addr = smem_to_u32(s_in);
    uint32_t swh_addr = smem_to_u32(s_wh);

    int n = blockIdx.x, by = blockIdx.y + by0;
    int tid = threadIdx.x, lane = tid & 31, wid = tid >> 5;
    int g = lane >> 2, tg = lane & 3;
    int row0 = by * RPT * STRIDE;

    int off0[NT];
    #pragma unroll
    for (int nt = 0; nt < NT; nt++) {
        int p = wid * (NT * 8) + nt * 8 + g;
        int r = p / WOUT, xx = p % WOUT;
        off0[nt] = (r * STRIDE) * 66 + xx * STRIDE;
    }

    for (int cb = 0; cb < CB; cb++) {
        float acc[2][NT][4] = {};
        for (int cib = 0; cib < KB; cib++) {
            if (cb + cib) __syncthreads();
            if (cb == 0) {
                const __half* inb = in + ((size_t)n * 4356 + row0 * 66) * CIN + cib * 32;
                for (int j = tid; j < NR * 66 * 4; j += 256) {
                    int rem = j >> 2, c8 = (j & 3) << 3;
                    uint32_t dst = sin_addr + (rem * 40 + c8) * 2;
                    const __half* src = inb + (size_t)rem * CIN + c8;
                    asm volatile("cp.async.cg.shared.global [%0], [%1], 16;"
                                 :: "r"(dst), "l"(src));
                }
            }
            for (int i = tid; i < 1440; i += 256) {
                int tap = i / 160, rem = i - tap * 160;
                size_t si = (((size_t)(cib * 9 + tap) * COUT + cb * 32) * 5 + rem) * 16;
                asm volatile("cp.async.cg.shared.global [%0], [%1], 16;"
                             :: "r"(swh_addr + i * 16), "l"((const char*)wph + si));
            }
            asm volatile("cp.async.commit_group;\ncp.async.wait_group 0;" ::: "memory");
            __syncthreads();

            #pragma unroll 3
            for (int tap = 0; tap < 9; tap++) {
                int dy = tap / 3, dx = tap - dy * 3;
                int drem = dy * 66 + dx;
                const __half* wh = s_wh + tap * 1280;
                #pragma unroll
                for (int kc = 0; kc < 2; kc++) {
                    uint32_t Ah[2][4];
                    #pragma unroll
                    for (int mt = 0; mt < 2; mt++) {
                        int a0 = (mt * 16 + g) * 40 + kc * 16 + tg * 2;
                        Ah[mt][0] = *(const uint32_t*)(wh + a0);
                        Ah[mt][1] = *(const uint32_t*)(wh + a0 + 320);
                        Ah[mt][2] = *(const uint32_t*)(wh + a0 + 8);
                        Ah[mt][3] = *(const uint32_t*)(wh + a0 + 328);
                    }
                    int cofs = kc * 16 + 2 * tg;
                    #pragma unroll
                    for (int nt = 0; nt < NT; nt++) {
                        int base = (off0[nt] + drem) * 40 + cofs;
                        uint32_t b0 = *(const uint32_t*)(s_in + base);
                        uint32_t b1 = *(const uint32_t*)(s_in + base + 8);
                        mma_f16(acc[0][nt], Ah[0][0], Ah[0][1], Ah[0][2], Ah[0][3], b0, b1);
                        mma_f16(acc[1][nt], Ah[1][0], Ah[1][1], Ah[1][2], Ah[1][3], b0, b1);
                    }
                }
            }
        }

        // epilogue for this cout block
        #pragma unroll
        for (int mt = 0; mt < 2; mt++) {
            int co = cb * 32 + mt * 16 + g;
            float bv0 = 0.f, bv1 = 0.f;
            if (HASBIAS) { bv0 = bias[co]; bv1 = bias[co + 8]; }
            #pragma unroll
            for (int nt = 0; nt < NT; nt++) {
                int p = wid * (NT * 8) + nt * 8 + 2 * tg;
                int r = p / WOUT, xx = p % WOUT;
                int oy = by * RPT + r;
                float v0 = acc[mt][nt][0] + bv0;
                float v1 = acc[mt][nt][1] + bv0;
                float v2 = acc[mt][nt][2] + bv1;
                float v3 = acc[mt][nt][3] + bv1;
                if (DOGELU) { v0 = gelu_f(v0); v1 = gelu_f(v1); v2 = gelu_f(v2); v3 = gelu_f(v3); }
                if (OM == 1) {
                    __half* o = (__half*)outv
                        + ((size_t)n * 4356 + (oy + 1) * 66 + (xx + 1)) * COUT + co;
                    o[0] = __float2half(v0); o[COUT] = __float2half(v1);
                    o[8] = __float2half(v2); o[COUT + 8] = __float2half(v3);
                } else if (OM == 2) {
                    __half* o = (__half*)outv + ((size_t)n * 4096 + oy * 64 + xx) * 32 + co;
                    o[0] = __float2half(v0); o[32] = __float2half(v1);
                    o[8] = __float2half(v2); o[40] = __float2half(v3);
                } else {
                    float* out = (float*)outv;
                    size_t oi = ((size_t)n * COUT + co) * (WOUT * WOUT) + oy * WOUT + xx;
                    size_t oi2 = oi + (size_t)8 * WOUT * WOUT;
                    if (RES) {
                        float2 r0 = *(const float2*)(res + oi);
                        float2 r1 = *(const float2*)(res + oi2);
                        v0 += r0.x; v1 += r0.y; v2 += r1.x; v3 += r1.y;
                    }
                    float2 w0; w0.x = v0; w0.y = v1;
                    float2 w1; w1.x = v2; w1.y = v3;
                    *(float2*)(out + oi)  = w0;
                    *(float2*)(out + oi2) = w1;
                }
            }
        }
    }
}

// ---------------------------------------------------------------------------
// QK scores, partial over d-quarter. grid=(32 bh, 4 dq), block=256 (8 warps).
// Stages q (transposed) + k chunks in smem: kq read ONCE per (bh,dq).
// scr[dq][bh][t][s] += sum over this quarter's 1024 d-values.
// ---------------------------------------------------------------------------
__global__ void qk_scores_kernel(const float* __restrict__ kq, float* __restrict__ scr) {
    int bh = blockIdx.x, dq = blockIdx.y;
    int b = bh >> 3, h = bh & 7;
    int tid = threadIdx.x, lane = tid & 31, w = tid >> 5;
    extern __shared__ __align__(16) float sm[];
    float* q_t = sm;                  // [256][33]
    float* kk  = sm + 256 * 33;       // [32][256]

    float acc[4] = {0.f, 0.f, 0.f, 0.f};
    for (int c = 0; c < 4; c++) {
        __syncthreads();
        for (int i = tid; i < 8192; i += 256) {
            int t = i >> 8, j = i & 255;
            q_t[j * 33 + t] = kq[((size_t)(b * 32 + t) * 64 + 32 + h * 4 + dq) * 1024
                                 + c * 256 + j];
        }
        for (int i = tid; i < 8192; i += 256) {
            int s = i >> 8, j = i & 255;
            kk[s * 256 + j] = kq[((size_t)(b * 32 + s) * 64 + h * 4 + dq) * 1024
                                 + c * 256 + j];
        }
        __syncthreads();
        for (int jj = 0; jj < 256; jj += 4) {
            float q0 = q_t[(jj + 0) * 33 + lane];
            float q1 = q_t[(jj + 1) * 33 + lane];
            float q2 = q_t[(jj + 2) * 33 + lane];
            float q3 = q_t[(jj + 3) * 33 + lane];
            #pragma unroll
            for (int si = 0; si < 4; si++) {
                float4 kv = *(const float4*)&kk[(w * 4 + si) * 256 + jj];
                acc[si] += q0 * kv.x + q1 * kv.y + q2 * kv.z + q3 * kv.w;
            }
        }
    }
    float4 o; o.x = acc[0]; o.y = acc[1]; o.z = acc[2]; o.w = acc[3];
    *(float4*)&scr[(((size_t)dq * 32 + bh) * 32 + lane) * 32 + w * 4] = o;
}

// ---------------------------------------------------------------------------
// softmax over summed partials. grid=32 (bh), block=1024 (warp = one t row).
// ---------------------------------------------------------------------------
__global__ void qk_softmax2_kernel(const float* __restrict__ scr, float* __restrict__ att) {
    int bh = blockIdx.x;
    int tid = threadIdx.x;
    int t = tid >> 5, s = tid & 31;
    size_t base = ((size_t)bh * 32 + t) * 32 + s;
    float v = (scr[base] + scr[base + 32768] + scr[base + 65536] + scr[base + 98304])
              * (1.f / 64.f);
    float m = v;
    #pragma unroll
    for (int o = 16; o > 0; o >>= 1) m = fmaxf(m, __shfl_xor_sync(0xffffffffu, m, o));
    float e = expf(v - m);
    float sum = e;
    #pragma unroll
    for (int o = 16; o > 0; o >>= 1) sum += __shfl_xor_sync(0xffffffffu, sum, o);
    att[base] = e / sum;
}

// ---------------------------------------------------------------------------
// y = att @ v. v fp16 channel-last; ypad fp16 padded channel-last.
// grid=(4,64), block=256 (lane=ci)
// ---------------------------------------------------------------------------
__global__ void av_kernel(const float* __restrict__ att, const __half* __restrict__ v,
                          __half* __restrict__ ypad) {
    int b = blockIdx.x, pc = blockIdx.y;
    int ci = threadIdx.x & 31, pl = threadIdx.x >> 5;
    int h = ci >> 2;
    __shared__ __align__(16) float sA[32][8][36];   // [s][h][t]
    for (int i = threadIdx.x; i < 8192; i += 256) {
        int s = i & 31, t = (i >> 5) & 31, hh = i >> 10;
        sA[s][hh][t] = att[(((size_t)(b * 8 + hh) * 32 + t) * 32) + s];
    }
    __syncthreads();
    for (int pp = 0; pp < 8; pp++) {
        int px = pc * 64 + pp * 8 + pl;
        float acc[32];
        #pragma unroll
        for (int t = 0; t < 32; t++) acc[t] = 0.f;
        const __half* vb = v + ((size_t)(b * 32) * 4096 + px) * 32 + ci;
        #pragma unroll 4
        for (int s = 0; s < 32; s++) {
            float vv = __half2float(vb[(size_t)s * 131072]);
            const float4* a4 = (const float4*)&sA[s][h][0];
            #pragma unroll
            for (int t4 = 0; t4 < 8; t4++) {
                float4 a = a4[t4];
                acc[4 * t4 + 0] += a.x * vv;
                acc[4 * t4 + 1] += a.y * vv;
                acc[4 * t4 + 2] += a.z * vv;
                acc[4 * t4 + 3] += a.w * vv;
            }
        }
        int y = px >> 6, xx = px & 63;
        __half* yb = ypad + ((size_t)(b * 32) * 4356 + (y + 1) * 66 + (xx + 1)) * 32 + ci;
        #pragma unroll
        for (int t = 0; t < 32; t++) yb[(size_t)t * 4356 * 32] = __float2half(acc[t]);
    }
}

// ---------------------------------------------------------------------------
extern "C" void kernel_launch(void* const* d_in, const int* in_sizes, int n_in,
                              void* d_out, int out_size) {
    const float* x   = (const float*)d_in[0];
    const float* n1g = (const float*)d_in[1];
    const float* n1b = (const float*)d_in[2];
    const float* n2g = (const float*)d_in[3];
    const float* n2b = (const float*)d_in[4];
    const float* Wk  = (const float*)d_in[5];
    const float* Wq  = (const float*)d_in[6];
    const float* Wv  = (const float*)d_in[7];
    const float* Wo  = (const float*)d_in[8];
    const float* bo  = (const float*)d_in[9];
    const float* Wm1 = (const float*)d_in[10];
    const float* bm1 = (const float*)d_in[11];
    const float* Wm2 = (const float*)d_in[12];
    const float* bm2 = (const float*)d_in[13];
    float* out = (float*)d_out;

    __half *xpad, *ypad, *hpad, *v, *wb;
    float *kq, *scr, *att, *x1;
    cudaGetSymbolAddress((void**)&xpad, g_xpad);
    cudaGetSymbolAddress((void**)&ypad, g_ypad);
    cudaGetSymbolAddress((void**)&hpad, g_hpad);
    cudaGetSymbolAddress((void**)&v,    g_v);
    cudaGetSymbolAddress((void**)&kq,   g_kq);
    cudaGetSymbolAddress((void**)&scr,  g_scr);
    cudaGetSymbolAddress((void**)&att,  g_att);
    cudaGetSymbolAddress((void**)&x1,   g_x1);
    cudaGetSymbolAddress((void**)&wb,   g_wb);

    __half *wv  = wb + 0 * WSTRIDE;
    __half *wkq = wb + 1 * WSTRIDE;
    __half *wo  = wb + 2 * WSTRIDE;
    __half *w1  = wb + 3 * WSTRIDE;
    __half *w2  = wb + 4 * WSTRIDE;

    // smem: s1 NT=8 (NR=10): in 10*66*40*2=52800 + w 23040 = 75840
    //       s2 NT=2 (NR=9):  in 9*66*40*2=47520 + w 23040 = 70560
    const int SM1 = 75840;
    const int SM2 = 70560;
    const int SMQK = (256 * 33 + 32 * 256) * 4;   // 66560
    cudaFuncSetAttribute(convT<32, 32, 1, 8, 1, false, false, false, 2>,
                         cudaFuncAttributeMaxDynamicSharedMemorySize, SM1);
    cudaFuncSetAttribute(convT<32, 64, 2, 2, 2, false, false, false, 0>,
                         cudaFuncAttributeMaxDynamicSharedMemorySize, SM2);
    cudaFuncSetAttribute(convT<32, 32, 1, 8, 1, true, false, true, 0>,
                         cudaFuncAttributeMaxDynamicSharedMemorySize, SM1);
    cudaFuncSetAttribute(convT<32, 128, 1, 8, 4, true, true, false, 1>,
                         cudaFuncAttributeMaxDynamicSharedMemorySize, SM1);
    cudaFuncSetAttribute(convT<128, 32, 1, 8, 1, true, false, true, 0>,
                         cudaFuncAttributeMaxDynamicSharedMemorySize, SM1);
    cudaFuncSetAttribute(qk_scores_kernel,
                         cudaFuncAttributeMaxDynamicSharedMemorySize, SMQK);

    // 11 launches
    wprep_all<<<(138240 + 255) / 256, 256>>>(Wv, Wk, Wq, Wo, Wm1, Wm2, wb);          // 0
    ln_pad_kernel<<<128, 256>>>(x, n1g, n1b, xpad);                                  // 1
    convT<32, 32, 1, 8, 1, false, false, false, 2>
        <<<dim3(128, 8), 256, SM1>>>(xpad, wv, nullptr, nullptr, v, 0);              // 2
    convT<32, 64, 2, 2, 2, false, false, false, 0>
        <<<dim3(128, 8), 256, SM2>>>(xpad, wkq, nullptr, nullptr, kq, 0);            // 3
    qk_scores_kernel<<<dim3(32, 4), 256, SMQK>>>(kq, scr);                           // 4
    qk_softmax2_kernel<<<32, 1024>>>(scr, att);                                      // 5
    av_kernel<<<dim3(4, 64), 256>>>(att, v, ypad);                                   // 6
    convT<32, 32, 1, 8, 1, true, false, true, 0>
        <<<dim3(128, 8), 256, SM1>>>(ypad, wo, bo, x, x1, 0);                        // 7
    ln_pad_kernel<<<128, 256>>>(x1, n2g, n2b, xpad);                                 // 8
    convT<32, 128, 1, 8, 4, true, true, false, 1>
        <<<dim3(128, 8), 256, SM1>>>(xpad, w1, bm1, nullptr, hpad, 0);               // 9
    convT<128, 32, 1, 8, 1, true, false, true, 0>
        <<<dim3(128, 8), 256, SM1>>>(hpad, w2, bm2, x1, out, 0);                     // 10
}

// round 16
// speedup vs baseline: 1.0356x; 1.0356x over previous
#include <cuda_runtime.h>
#include <cuda_fp16.h>
#include <math.h>
#include <cstdint>

// ===========================================================================
// STCNNT cell, convs as implicit GEMM on mma.sync (HMMA fp16 single product,
// fp32 accum). Activations fp16 CHANNEL-LAST [n][row][col][ci].
// Round-13 base + double-buffered weight prefetch on ALL multi-stage convs
// (kq/m1/m2). Single-stage convs (v/o) use one buffer.
// B=4, T=32 (BT=128), C=32, H=W=64, mixer=128, n_head=8
// ===========================================================================

#define BT 128

// ---------------- device scratch (zero-initialized at module load) ---------
__device__ __half g_xpad[BT * 66 * 66 * 32];     // fp16 padded channel-last
__device__ __half g_ypad[BT * 66 * 66 * 32];
__device__ __half g_hpad[BT * 66 * 66 * 128];
__device__ float  g_v  [BT * 64 * 64 * 32];      // fp32 channel-last
__device__ float  g_kq [BT * 64 * 32 * 32];      // [n][64: k=0-31,q=32-63][32][32]
__device__ float  g_att[4 * 8 * 32 * 32];
__device__ float  g_x1 [BT * 32 * 64 * 64];      // standard layout
#define WSTRIDE 46080   // halfs per conv slot: max KB*9*COUT*40
__device__ __align__(16) __half g_wb[5 * WSTRIDE];

__device__ __forceinline__ float gelu_f(float v) {
    float u = 0.7978845608028654f * (v + 0.044715f * v * v * v);
    return 0.5f * v * (1.0f + tanhf(u));
}

__device__ __forceinline__ uint32_t smem_to_u32(const void* p) {
    uint32_t a;
    asm("{ .reg .u64 t; cvta.to.shared.u64 t, %1; cvt.u32.u64 %0, t; }" : "=r"(a) : "l"(p));
    return a;
}

__device__ __forceinline__ void mma_f16(float* c, uint32_t a0, uint32_t a1,
                                        uint32_t a2, uint32_t a3,
                                        uint32_t b0, uint32_t b1) {
    asm volatile(
        "mma.sync.aligned.m16n8k16.row.col.f32.f16.f16.f32 "
        "{%0,%1,%2,%3}, {%4,%5,%6,%7}, {%8,%9}, {%0,%1,%2,%3};"
        : "+f"(c[0]), "+f"(c[1]), "+f"(c[2]), "+f"(c[3])
        : "r"(a0), "r"(a1), "r"(a2), "r"(a3), "r"(b0), "r"(b1));
}

#define CP_ASYNC16(dst, src) \
    asm volatile("cp.async.cg.shared.global [%0], [%1], 16;" :: "r"(dst), "l"(src))
#define CP_COMMIT() asm volatile("cp.async.commit_group;" ::: "memory")
#define CP_WAIT0()  asm volatile("cp.async.wait_group 0;" ::: "memory")

// ---------------------------------------------------------------------------
// merged weight prep: fp32 [cout][Cin][3][3] -> fp16 planes for all 5 slots,
// layout [cib][tap][COUTL][40] (k 0..31 real, 32..39 zero)
// ---------------------------------------------------------------------------
__device__ __forceinline__ void wprep_one(const float* w, __half* dstp, int idx,
                                          int CIN, int COUTL, int cout0, int NCO) {
    int kk = idx % 40;
    int t1 = idx / 40;
    int cout = t1 % NCO;
    int t2 = t1 / NCO;
    int tap = t2 % 9, cib = t2 / 9;
    float wv = (kk < 32) ? w[((size_t)cout * CIN + cib * 32 + kk) * 9 + tap] : 0.f;
    dstp[((size_t)(cib * 9 + tap) * COUTL + cout0 + cout) * 40 + kk] = __float2half_rn(wv);
}

__global__ void wprep_all(const float* __restrict__ Wv, const float* __restrict__ Wk,
                          const float* __restrict__ Wq, const float* __restrict__ Wo,
                          const float* __restrict__ Wm1, const float* __restrict__ Wm2,
                          __half* __restrict__ wb) {
    int idx = blockIdx.x * blockDim.x + threadIdx.x;
    if (idx < 11520) {
        wprep_one(Wv, wb + 0 * WSTRIDE, idx, 32, 32, 0, 32);
    } else if (idx < 23040) {
        wprep_one(Wk, wb + 1 * WSTRIDE, idx - 11520, 32, 64, 0, 32);
    } else if (idx < 34560) {
        wprep_one(Wq, wb + 1 * WSTRIDE, idx - 23040, 32, 64, 32, 32);
    } else if (idx < 46080) {
        wprep_one(Wo, wb + 2 * WSTRIDE, idx - 34560, 32, 32, 0, 32);
    } else if (idx < 92160) {
        wprep_one(Wm1, wb + 3 * WSTRIDE, idx - 46080, 32, 128, 0, 128);
    } else if (idx < 138240) {
        wprep_one(Wm2, wb + 4 * WSTRIDE, idx - 92160, 128, 32, 0, 32);
    }
}

// ---------------------------------------------------------------------------
// LayerNorm over (C,H,W)=131072 -> fp16 padded CHANNEL-LAST [n][66][66][32]
// grid=128, block=256
// ---------------------------------------------------------------------------
__global__ void ln_pad_kernel(const float* __restrict__ x, const float* __restrict__ g,
                              const float* __restrict__ b, __half* __restrict__ out) {
    int n = blockIdx.x;
    const float* xb = x + (size_t)n * 131072;
    const float4* x4 = (const float4*)xb;
    float s = 0.f, ss = 0.f;
    for (int i = threadIdx.x; i < 32768; i += 256) {
        float4 v = x4[i];
        s  += v.x + v.y + v.z + v.w;
        ss += v.x * v.x + v.y * v.y + v.z * v.z + v.w * v.w;
    }
    __shared__ float rs[8], rss[8];
    #pragma unroll
    for (int o = 16; o > 0; o >>= 1) {
        s  += __shfl_xor_sync(0xffffffffu, s, o);
        ss += __shfl_xor_sync(0xffffffffu, ss, o);
    }
    int wrp = threadIdx.x >> 5, lane = threadIdx.x & 31;
    if (lane == 0) { rs[wrp] = s; rss[wrp] = ss; }
    __syncthreads();
    if (threadIdx.x < 32) {
        s  = (threadIdx.x < 8) ? rs[threadIdx.x]  : 0.f;
        ss = (threadIdx.x < 8) ? rss[threadIdx.x] : 0.f;
        #pragma unroll
        for (int o = 4; o > 0; o >>= 1) {
            s  += __shfl_xor_sync(0xffffffffu, s, o);
            ss += __shfl_xor_sync(0xffffffffu, ss, o);
        }
        if (threadIdx.x == 0) { rs[0] = s; rss[0] = ss; }
    }
    __syncthreads();
    float mean = rs[0] * (1.f / 131072.f);
    float var  = rss[0] * (1.f / 131072.f) - mean * mean;
    float rstd = rsqrtf(var + 1e-5f);

    __shared__ float tile[32][33];
    __half* ob = out + (size_t)n * 4356 * 32;
    for (int t0 = 0; t0 < 4096; t0 += 32) {
        __syncthreads();
        #pragma unroll
        for (int cc = 0; cc < 4; cc++) {
            int ci = wrp * 4 + cc;
            int px = t0 + lane;
            size_t e = (size_t)ci * 4096 + px;
            tile[ci][lane] = (xb[e] - mean) * rstd * __ldg(g + e) + __ldg(b + e);
        }
        __syncthreads();
        #pragma unroll
        for (int cc = 0; cc < 4; cc++) {
            int pxl = wrp * 4 + cc;
            int px = t0 + pxl;
            int y = px >> 6, xx = px & 63;
            ob[((y + 1) * 66 + (xx + 1)) * 32 + lane] = __float2half(tile[lane][pxl]);
        }
    }
}

// ---------------------------------------------------------------------------
// HMMA implicit-GEMM 3x3 conv. Input fp16 padded CHANNEL-LAST [n][66][66][CIN].
// grid=(128, ytiles), block=256 (8 warps). Stages = CB*(CIN/32).
// WDB: double-buffered weight smem with cross-stage prefetch (REQUIRED when
// ST > 1 — the non-WDB path loads weights only for stage 0).
// OM: 0 = fp32 standard out (+res), 1 = fp16 padded channel-last, 2 = fp32 channel-last
// ---------------------------------------------------------------------------
template<int CIN, int COUT, int STRIDE, int NT, int CB, bool WDB,
         bool HASBIAS, bool DOGELU, bool RES, int OM>
__global__ void __launch_bounds__(256) convT(
    const __half* __restrict__ in,
    const __half* __restrict__ wph,
    const float* __restrict__ bias,
    const float* __restrict__ res,
    void* __restrict__ outv, int by0) {

    constexpr int WOUT  = 64 / STRIDE;
    constexpr int PIX   = NT * 64;
    constexpr int RPT   = PIX / WOUT;
    constexpr int NR    = (RPT - 1) * STRIDE + 3;
    constexpr int KB    = CIN / 32;
    constexpr int ST    = CB * KB;
    static_assert(ST == 1 || WDB, "multi-stage conv requires WDB weight prefetch");
    constexpr int S_INH = NR * 66 * 40;   // halfs
    constexpr int S_WH  = 9 * 32 * 40;    // halfs per weight buffer

    extern __shared__ __align__(16) __half smem[];
    __half* s_in = smem;
    __half* s_wh = smem + S_INH;
    uint32_t sin_addr = smem_to_u32(s_in);
    uint32_t swh_addr = smem_to_u32(s_wh);

    int n = blockIdx.x, by = blockIdx.y + by0;
    int tid = threadIdx.x, lane = tid & 31, wid = tid >> 5;
    int g = lane >> 2, tg = lane & 3;
    int row0 = by * RPT * STRIDE;

    int off0[NT];
    #pragma unroll
    for (int nt = 0; nt < NT; nt++) {
        int p = wid * (NT * 8) + nt * 8 + g;
        int r = p / WOUT, xx = p % WOUT;
        off0[nt] = (r * STRIDE) * 66 + xx * STRIDE;
    }

    auto issue_in = [&](int cib) {
        const __half* inb = in + ((size_t)n * 4356 + row0 * 66) * CIN + cib * 32;
        for (int j = tid; j < NR * 66 * 4; j += 256) {
            int rem = j >> 2, c8 = (j & 3) << 3;
            uint32_t dst = sin_addr + (rem * 40 + c8) * 2;
            const __half* src = inb + (size_t)rem * CIN + c8;
            CP_ASYNC16(dst, src);
        }
    };
    auto issue_w = [&](int s, int buf) {
        int cbs = s / KB, cibs = s - cbs * KB;
        uint32_t base = swh_addr + buf * (S_WH * 2);
        for (int i = tid; i < 1440; i += 256) {
            int tap = i / 160, rem = i - tap * 160;
            size_t si = (((size_t)(cibs * 9 + tap) * COUT + cbs * 32) * 5 + rem) * 16;
            CP_ASYNC16(base + i * 16, (const char*)wph + si);
        }
    };

    issue_in(0);
    issue_w(0, 0);
    CP_COMMIT();

    float acc[2][NT][4];

    for (int s = 0; s < ST; s++) {
        int cb = s / KB, cib = s - cb * KB;
        CP_WAIT0();
        __syncthreads();
        if (WDB && s + 1 < ST) { issue_w(s + 1, (s + 1) & 1); CP_COMMIT(); }
        if (cib == 0) {
            #pragma unroll
            for (int m = 0; m < 2; m++)
                #pragma unroll
                for (int nt = 0; nt < NT; nt++)
                    #pragma unroll
                    for (int j = 0; j < 4; j++) acc[m][nt][j] = 0.f;
        }
        const __half* wb = s_wh + (WDB ? (s & 1) * S_WH : 0);

        #pragma unroll 3
        for (int tap = 0; tap < 9; tap++) {
            int dy = tap / 3, dx = tap - dy * 3;
            int drem = dy * 66 + dx;
            const __half* wh = wb + tap * 1280;
            #pragma unroll
            for (int kc = 0; kc < 2; kc++) {
                uint32_t Ah[2][4];
                #pragma unroll
                for (int mt = 0; mt < 2; mt++) {
                    int a0 = (mt * 16 + g) * 40 + kc * 16 + tg * 2;
                    Ah[mt][0] = *(const uint32_t*)(wh + a0);
                    Ah[mt][1] = *(const uint32_t*)(wh + a0 + 320);
                    Ah[mt][2] = *(const uint32_t*)(wh + a0 + 8);
                    Ah[mt][3] = *(const uint32_t*)(wh + a0 + 328);
                }
                int cofs = kc * 16 + 2 * tg;
                #pragma unroll
                for (int nt = 0; nt < NT; nt++) {
                    int base = (off0[nt] + drem) * 40 + cofs;
                    uint32_t b0 = *(const uint32_t*)(s_in + base);
                    uint32_t b1 = *(const uint32_t*)(s_in + base + 8);
                    mma_f16(acc[0][nt], Ah[0][0], Ah[0][1], Ah[0][2], Ah[0][3], b0, b1);
                    mma_f16(acc[1][nt], Ah[1][0], Ah[1][1], Ah[1][2], Ah[1][3], b0, b1);
                }
            }
        }

        if (cib == KB - 1) {
            // epilogue for cout block cb
            #pragma unroll
            for (int mt = 0; mt < 2; mt++) {
                int co = cb * 32 + mt * 16 + g;
                float bv0 = 0.f, bv1 = 0.f;
                if (HASBIAS) { bv0 = bias[co]; bv1 = bias[co + 8]; }
                #pragma unroll
                for (int nt = 0; nt < NT; nt++) {
                    int p = wid * (NT * 8) + nt * 8 + 2 * tg;
                    int r = p / WOUT, xx = p % WOUT;
                    int oy = by * RPT + r;
                    float v0 = acc[mt][nt][0] + bv0;
                    float v1 = acc[mt][nt][1] + bv0;
                    float v2 = acc[mt][nt][2] + bv1;
                    float v3 = acc[mt][nt][3] + bv1;
                    if (DOGELU) { v0 = gelu_f(v0); v1 = gelu_f(v1);
                                  v2 = gelu_f(v2); v3 = gelu_f(v3); }
                    if (OM == 1) {
                        __half* o = (__half*)outv
                            + ((size_t)n * 4356 + (oy + 1) * 66 + (xx + 1)) * COUT + co;
                        o[0] = __float2half(v0); o[COUT] = __float2half(v1);
                        o[8] = __float2half(v2); o[COUT + 8] = __float2half(v3);
                    } else if (OM == 2) {
                        float* o = (float*)outv + ((size_t)n * 4096 + oy * 64 + xx) * 32 + co;
                        o[0] = v0; o[32] = v1; o[8] = v2; o[40] = v3;
                    } else {
                        float* out = (float*)outv;
                        size_t oi = ((size_t)n * COUT + co) * (WOUT * WOUT) + oy * WOUT + xx;
                        size_t oi2 = oi + (size_t)8 * WOUT * WOUT;
                        if (RES) {
                            float2 r0 = *(const float2*)(res + oi);
                            float2 r1 = *(const float2*)(res + oi2);
                            v0 += r0.x; v1 += r0.y; v2 += r1.x; v3 += r1.y;
                        }
                        float2 w0; w0.x = v0; w0.y = v1;
                        float2 w1; w1.x = v2; w1.y = v3;
                        *(float2*)(out + oi)  = w0;
                        *(float2*)(out + oi2) = w1;
                    }
                }
            }
        }

        if (KB > 1 && s + 1 < ST) {
            __syncthreads();
            issue_in((s + 1) % KB);
            CP_COMMIT();
        }
    }
}

// ---------------------------------------------------------------------------
// att = softmax(q.k/64); merged kq: [n][64][32][32], k=couts 0-31, q=32-63
// grid=1024, block=256
// ---------------------------------------------------------------------------
__global__ void qk_softmax_kernel(const float* __restrict__ kq, float* __restrict__ att) {
    int bx = blockIdx.x;
    int t = bx & 31, bh = bx >> 5, h = bh & 7, b = bh >> 3;
    int lane = threadIdx.x & 31, w = threadIdx.x >> 5;
    const float4* q4 = (const float4*)(kq + ((size_t)(b * 32 + t) * 64 + 32 + h * 4) * 1024);
    __shared__ float sS[32];
    #pragma unroll
    for (int si = 0; si < 4; si++) {
        int s = w * 4 + si;
        const float4* k4 = (const float4*)(kq + ((size_t)(b * 32 + s) * 64 + h * 4) * 1024);
        float acc = 0.f;
        for (int d = lane; d < 1024; d += 32) {
            float4 qv = q4[d], kv = k4[d];
            acc += qv.x * kv.x + qv.y * kv.y + qv.z * kv.z + qv.w * kv.w;
        }
        #pragma unroll
        for (int o = 16; o > 0; o >>= 1) acc += __shfl_xor_sync(0xffffffffu, acc, o);
        if (lane == 0) sS[s] = acc * (1.f / 64.f);
    }
    __syncthreads();
    if (threadIdx.x < 32) {
        float v = sS[threadIdx.x];
        float m = v;
        #pragma unroll
        for (int o = 16; o > 0; o >>= 1) m = fmaxf(m, __shfl_xor_sync(0xffffffffu, m, o));
        float e = expf(v - m);
        float sum = e;
        #pragma unroll
        for (int o = 16; o > 0; o >>= 1) sum += __shfl_xor_sync(0xffffffffu, sum, o);
        att[(size_t)bx * 32 + threadIdx.x] = e / sum;
    }
}

// ---------------------------------------------------------------------------
// y = att @ v. v fp32 channel-last; ypad fp16 padded channel-last.
// grid=(4,64), block=256 (lane=ci)
// ---------------------------------------------------------------------------
__global__ void av_kernel(const float* __restrict__ att, const float* __restrict__ v,
                          __half* __restrict__ ypad) {
    int b = blockIdx.x, pc = blockIdx.y;
    int ci = threadIdx.x & 31, pl = threadIdx.x >> 5;
    int h = ci >> 2;
    __shared__ __align__(16) float sA[32][8][36];   // [s][h][t]
    for (int i = threadIdx.x; i < 8192; i += 256) {
        int s = i & 31, t = (i >> 5) & 31, hh = i >> 10;
        sA[s][hh][t] = att[(((size_t)(b * 8 + hh) * 32 + t) * 32) + s];
    }
    __syncthreads();
    for (int pp = 0; pp < 8; pp++) {
        int px = pc * 64 + pp * 8 + pl;
        float acc[32];
        #pragma unroll
        for (int t = 0; t < 32; t++) acc[t] = 0.f;
        const float* vb = v + ((size_t)(b * 32) * 4096 + px) * 32 + ci;
        #pragma unroll 4
        for (int s = 0; s < 32; s++) {
            float vv = vb[(size_t)s * 131072];
            const float4* a4 = (const float4*)&sA[s][h][0];
            #pragma unroll
            for (int t4 = 0; t4 < 8; t4++) {
                float4 a = a4[t4];
                acc[4 * t4 + 0] += a.x * vv;
                acc[4 * t4 + 1] += a.y * vv;
                acc[4 * t4 + 2] += a.z * vv;
                acc[4 * t4 + 3] += a.w * vv;
            }
        }
        int y = px >> 6, xx = px & 63;
        __half* yb = ypad + ((size_t)(b * 32) * 4356 + (y + 1) * 66 + (xx + 1)) * 32 + ci;
        #pragma unroll
        for (int t = 0; t < 32; t++) yb[(size_t)t * 4356 * 32] = __float2half(acc[t]);
    }
}

// ---------------------------------------------------------------------------
extern "C" void kernel_launch(void* const* d_in, const int* in_sizes, int n_in,
                              void* d_out, int out_size) {
    const float* x   = (const float*)d_in[0];
    const float* n1g = (const float*)d_in[1];
    const float* n1b = (const float*)d_in[2];
    const float* n2g = (const float*)d_in[3];
    const float* n2b = (const float*)d_in[4];
    const float* Wk  = (const float*)d_in[5];
    const float* Wq  = (const float*)d_in[6];
    const float* Wv  = (const float*)d_in[7];
    const float* Wo  = (const float*)d_in[8];
    const float* bo  = (const float*)d_in[9];
    const float* Wm1 = (const float*)d_in[10];
    const float* bm1 = (const float*)d_in[11];
    const float* Wm2 = (const float*)d_in[12];
    const float* bm2 = (const float*)d_in[13];
    float* out = (float*)d_out;

    __half *xpad, *ypad, *hpad, *wb;
    float *v, *kq, *att, *x1;
    cudaGetSymbolAddress((void**)&xpad, g_xpad);
    cudaGetSymbolAddress((void**)&ypad, g_ypad);
    cudaGetSymbolAddress((void**)&hpad, g_hpad);
    cudaGetSymbolAddress((void**)&v,    g_v);
    cudaGetSymbolAddress((void**)&kq,   g_kq);
    cudaGetSymbolAddress((void**)&att,  g_att);
    cudaGetSymbolAddress((void**)&x1,   g_x1);
    cudaGetSymbolAddress((void**)&wb,   g_wb);

    __half *wv  = wb + 0 * WSTRIDE;
    __half *wkq = wb + 1 * WSTRIDE;
    __half *wo  = wb + 2 * WSTRIDE;
    __half *w1  = wb + 3 * WSTRIDE;
    __half *w2  = wb + 4 * WSTRIDE;

    // smem: s1 NT=8 (NR=10): in 52800 + w 23040 = 75840 (single buffer)
    //       s1 NT=8 WDB:     in 52800 + 2*23040 = 98880
    //       s2 NT=2 WDB:     in 47520 + 2*23040 = 93600
    const int SM1  = 75840;
    const int SM1D = 98880;
    const int SM2D = 93600;
    cudaFuncSetAttribute(convT<32, 32, 1, 8, 1, false, false, false, false, 2>,
                         cudaFuncAttributeMaxDynamicSharedMemorySize, SM1);
    cudaFuncSetAttribute(convT<32, 64, 2, 2, 2, true, false, false, false, 0>,
                         cudaFuncAttributeMaxDynamicSharedMemorySize, SM2D);
    cudaFuncSetAttribute(convT<32, 32, 1, 8, 1, false, true, false, true, 0>,
                         cudaFuncAttributeMaxDynamicSharedMemorySize, SM1);
    cudaFuncSetAttribute(convT<32, 128, 1, 8, 4, true, true, true, false, 1>,
                         cudaFuncAttributeMaxDynamicSharedMemorySize, SM1D);
    cudaFuncSetAttribute(convT<128, 32, 1, 8, 1, true, true, false, true, 0>,
                         cudaFuncAttributeMaxDynamicSharedMemorySize, SM1D);

    // 10 launches
    wprep_all<<<(138240 + 255) / 256, 256>>>(Wv, Wk, Wq, Wo, Wm1, Wm2, wb);          // 0
    ln_pad_kernel<<<128, 256>>>(x, n1g, n1b, xpad);                                  // 1
    convT<32, 32, 1, 8, 1, false, false, false, false, 2>
        <<<dim3(128, 8), 256, SM1>>>(xpad, wv, nullptr, nullptr, v, 0);              // 2
    convT<32, 64, 2, 2, 2, true, false, false, false, 0>
        <<<dim3(128, 8), 256, SM2D>>>(xpad, wkq, nullptr, nullptr, kq, 0);           // 3
    qk_softmax_kernel<<<1024, 256>>>(kq, att);                                       // 4
    av_kernel<<<dim3(4, 64), 256>>>(att, v, ypad);                                   // 5
    convT<32, 32, 1, 8, 1, false, true, false, true, 0>
        <<<dim3(128, 8), 256, SM1>>>(ypad, wo, bo, x, x1, 0);                        // 6
    ln_pad_kernel<<<128, 256>>>(x1, n2g, n2b, xpad);                                 // 7
    convT<32, 128, 1, 8, 4, true, true, true, false, 1>
        <<<dim3(128, 8), 256, SM1D>>>(xpad, w1, bm1, nullptr, hpad, 0);              // 8
    convT<128, 32, 1, 8, 1, true, true, false, true, 0>
        <<<dim3(128, 8), 256, SM1D>>>(hpad, w2, bm2, x1, out, 0);                    // 9
}